// round 10
// baseline (speedup 1.0000x reference)
#include <cuda_runtime.h>
#include <math.h>
#include <stdint.h>

#define NN 12288
#define DD 128
#define KK 20
#define HID 128
#define OUTD 64
#define E_TOT (NN*(KK+1))
#define CAP 768
#define THRESH 0.18f
#define FB_BLOCKS 148
#define NB 96                      // NN/128 tile count
#define TRI_BLOCKS (NB*(NB+1)/2)   // 4656

// ---------------- scratch (device globals; no allocations allowed) ----------------
__device__ float g_xn[NN*DD];                     // fp32 normalized (exact path)
__device__ float g_xhi[NN*DD];                    // tf32 hi part
__device__ float g_xlo[NN*DD];                    // tf32 lo part
__device__ unsigned int g_cval[(size_t)NN*CAP];
__device__ unsigned int g_ccol[(size_t)NN*CAP];
__device__ int   g_ccnt[NN];
__device__ int   g_fbcnt;
__device__ int   g_fblist[NN];
__device__ float g_fbrow[(size_t)FB_BLOCKS*NN];
__device__ float g_topv[NN*KK];
__device__ int   g_topi[NN*KK];
__device__ float g_deg[NN];
__device__ float g_dis[NN];
__device__ int   g_cnt[NN];
__device__ int   g_off[NN+1];
__device__ int   g_fill[NN];
__device__ int   g_esrc[E_TOT];
__device__ float g_ew[E_TOT];
__device__ float g_hw1[NN*HID];
__device__ float g_h[NN*HID];
__device__ float g_hw2[NN*OUTD];

__device__ __forceinline__ unsigned int ordmap(float f) {
    unsigned int b = __float_as_uint(f);
    return (b & 0x80000000u) ? ~b : (b | 0x80000000u);
}
__device__ __forceinline__ float ordunmap(unsigned int u) {
    unsigned int b = (u & 0x80000000u) ? (u ^ 0x80000000u) : ~u;
    return __uint_as_float(b);
}
__device__ __forceinline__ unsigned int to_tf32(float v) {
    unsigned int r;
    asm("cvt.rna.tf32.f32 %0, %1;" : "=r"(r) : "f"(v));
    return r;
}
__device__ __forceinline__ void mma_tf32(float* c, const unsigned* a, const unsigned* b) {
    asm volatile("mma.sync.aligned.m16n8k8.row.col.f32.tf32.tf32.f32 "
        "{%0,%1,%2,%3}, {%4,%5,%6,%7}, {%8,%9}, {%0,%1,%2,%3};"
        : "+f"(c[0]), "+f"(c[1]), "+f"(c[2]), "+f"(c[3])
        : "r"(a[0]), "r"(a[1]), "r"(a[2]), "r"(a[3]), "r"(b[0]), "r"(b[1]));
}

// ---------------- 1. row-normalize x + tf32 hi/lo split ----------------
__global__ void normalize_kernel(const float* __restrict__ x) {
    int warp = (blockIdx.x * blockDim.x + threadIdx.x) >> 5;
    int lane = threadIdx.x & 31;
    if (warp >= NN) return;
    const float4* xr = (const float4*)(x + (size_t)warp * DD);
    float4 v = xr[lane];
    float ss = v.x*v.x + v.y*v.y + v.z*v.z + v.w*v.w;
    #pragma unroll
    for (int o = 16; o; o >>= 1) ss += __shfl_xor_sync(0xffffffffu, ss, o);
    float inv = 1.0f / fmaxf(sqrtf(ss), 1e-12f);
    float4 o4 = make_float4(v.x*inv, v.y*inv, v.z*inv, v.w*inv);
    ((float4*)(g_xn + (size_t)warp*DD))[lane] = o4;
    float4 h4, l4;
    {
        h4.x = __uint_as_float(to_tf32(o4.x)); l4.x = __uint_as_float(to_tf32(o4.x - h4.x));
        h4.y = __uint_as_float(to_tf32(o4.y)); l4.y = __uint_as_float(to_tf32(o4.y - h4.y));
        h4.z = __uint_as_float(to_tf32(o4.z)); l4.z = __uint_as_float(to_tf32(o4.z - h4.z));
        h4.w = __uint_as_float(to_tf32(o4.w)); l4.w = __uint_as_float(to_tf32(o4.w - h4.w));
    }
    ((float4*)(g_xhi + (size_t)warp*DD))[lane] = h4;
    ((float4*)(g_xlo + (size_t)warp*DD))[lane] = l4;
}

// ---------------- 2. init counters ----------------
__global__ void init_kernel() {
    int i = blockIdx.x * blockDim.x + threadIdx.x;
    if (i < NN) { g_deg[i] = 0.f; g_cnt[i] = 0; g_ccnt[i] = 0; }
    if (i == 0) g_fbcnt = 0;
}

// ---------------- 3. symmetric 3xTF32 tensor GEMM: candidate SCREENING ----------------
__global__ void __launch_bounds__(256) gemm_cand_kernel() {
    __shared__ __align__(16) float sAhi[2][8][128];
    __shared__ __align__(16) float sAlo[2][8][128];
    __shared__ __align__(16) float sBhi[2][16][64];
    __shared__ __align__(16) float sBlo[2][16][64];

    int bid = blockIdx.x;
    int by = (int)(96.5f - sqrtf(96.5f*96.5f - 2.0f*(float)bid));
    while (NB*by - by*(by-1)/2 > bid) by--;
    while (NB*(by+1) - (by+1)*by/2 <= bid) by++;
    int bx = by + bid - (NB*by - by*(by-1)/2);

    int tid = threadIdx.x;
    int wid = tid >> 5, lane = tid & 31;
    int wr = wid & 3;
    int wc = wid >> 2;
    int rowBase = by * 128, colBase = bx * 128;

    int lrow = tid >> 1;
    int lkq  = tid & 1;
    const float* ahp = g_xhi + (size_t)(rowBase + lrow) * DD + lkq*4;
    const float* alp = g_xlo + (size_t)(rowBase + lrow) * DD + lkq*4;
    const float* bhp = g_xhi + (size_t)(colBase + lrow) * DD + lkq*4;
    const float* blp = g_xlo + (size_t)(colBase + lrow) * DD + lkq*4;

    int a_mf = lrow >> 4;
    int a_r  = lrow & 15;
    int a_lt = (a_r & 7) * 4;
    int a_sl = (a_r >> 3) + 2 * lkq;
    int b_nf = lrow >> 3;
    int b_g  = (lrow & 7) * 4;

    {
        float4 ah = *(const float4*)ahp;
        float4 al = *(const float4*)alp;
        float4 bh = *(const float4*)bhp;
        float4 bl = *(const float4*)blp;
        sAhi[0][a_mf][(a_lt+0)*4 + a_sl] = ah.x; sAhi[0][a_mf][(a_lt+1)*4 + a_sl] = ah.y;
        sAhi[0][a_mf][(a_lt+2)*4 + a_sl] = ah.z; sAhi[0][a_mf][(a_lt+3)*4 + a_sl] = ah.w;
        sAlo[0][a_mf][(a_lt+0)*4 + a_sl] = al.x; sAlo[0][a_mf][(a_lt+1)*4 + a_sl] = al.y;
        sAlo[0][a_mf][(a_lt+2)*4 + a_sl] = al.z; sAlo[0][a_mf][(a_lt+3)*4 + a_sl] = al.w;
        sBhi[0][b_nf][(b_g+0)*2 + lkq] = bh.x; sBhi[0][b_nf][(b_g+1)*2 + lkq] = bh.y;
        sBhi[0][b_nf][(b_g+2)*2 + lkq] = bh.z; sBhi[0][b_nf][(b_g+3)*2 + lkq] = bh.w;
        sBlo[0][b_nf][(b_g+0)*2 + lkq] = bl.x; sBlo[0][b_nf][(b_g+1)*2 + lkq] = bl.y;
        sBlo[0][b_nf][(b_g+2)*2 + lkq] = bl.z; sBlo[0][b_nf][(b_g+3)*2 + lkq] = bl.w;
    }
    __syncthreads();

    float acc[2][8][4];
    #pragma unroll
    for (int f = 0; f < 2; f++)
        #pragma unroll
        for (int n = 0; n < 8; n++)
            #pragma unroll
            for (int e = 0; e < 4; e++) acc[f][n][e] = 0.f;

    int buf = 0;
    #pragma unroll 1
    for (int s = 0; s < 16; s++) {
        float4 ah, al, bh, bl;
        if (s < 15) {
            ah = *(const float4*)(ahp + (s+1)*8);
            al = *(const float4*)(alp + (s+1)*8);
            bh = *(const float4*)(bhp + (s+1)*8);
            bl = *(const float4*)(blp + (s+1)*8);
        }
        unsigned afh[2][4], afl[2][4];
        #pragma unroll
        for (int f = 0; f < 2; f++) {
            float4 vh = *(const float4*)&sAhi[buf][wr*2+f][lane*4];
            float4 vl = *(const float4*)&sAlo[buf][wr*2+f][lane*4];
            afh[f][0]=__float_as_uint(vh.x); afh[f][1]=__float_as_uint(vh.y);
            afh[f][2]=__float_as_uint(vh.z); afh[f][3]=__float_as_uint(vh.w);
            afl[f][0]=__float_as_uint(vl.x); afl[f][1]=__float_as_uint(vl.y);
            afl[f][2]=__float_as_uint(vl.z); afl[f][3]=__float_as_uint(vl.w);
        }
        #pragma unroll
        for (int n = 0; n < 8; n++) {
            float2 wh = *(const float2*)&sBhi[buf][wc*8+n][lane*2];
            float2 wl = *(const float2*)&sBlo[buf][wc*8+n][lane*2];
            unsigned bfh[2] = { __float_as_uint(wh.x), __float_as_uint(wh.y) };
            unsigned bfl[2] = { __float_as_uint(wl.x), __float_as_uint(wl.y) };
            #pragma unroll
            for (int f = 0; f < 2; f++) {
                mma_tf32(acc[f][n], afh[f], bfh);
                mma_tf32(acc[f][n], afh[f], bfl);
                mma_tf32(acc[f][n], afl[f], bfh);
            }
        }
        if (s < 15) {
            int nb = buf ^ 1;
            sAhi[nb][a_mf][(a_lt+0)*4 + a_sl] = ah.x; sAhi[nb][a_mf][(a_lt+1)*4 + a_sl] = ah.y;
            sAhi[nb][a_mf][(a_lt+2)*4 + a_sl] = ah.z; sAhi[nb][a_mf][(a_lt+3)*4 + a_sl] = ah.w;
            sAlo[nb][a_mf][(a_lt+0)*4 + a_sl] = al.x; sAlo[nb][a_mf][(a_lt+1)*4 + a_sl] = al.y;
            sAlo[nb][a_mf][(a_lt+2)*4 + a_sl] = al.z; sAlo[nb][a_mf][(a_lt+3)*4 + a_sl] = al.w;
            sBhi[nb][b_nf][(b_g+0)*2 + lkq] = bh.x; sBhi[nb][b_nf][(b_g+1)*2 + lkq] = bh.y;
            sBhi[nb][b_nf][(b_g+2)*2 + lkq] = bh.z; sBhi[nb][b_nf][(b_g+3)*2 + lkq] = bh.w;
            sBlo[nb][b_nf][(b_g+0)*2 + lkq] = bl.x; sBlo[nb][b_nf][(b_g+1)*2 + lkq] = bl.y;
            sBlo[nb][b_nf][(b_g+2)*2 + lkq] = bl.z; sBlo[nb][b_nf][(b_g+3)*2 + lkq] = bl.w;
            buf = nb;
            __syncthreads();
        }
    }

    bool mirror = (bx > by);
    int g = lane >> 2, tg = lane & 3;
    #pragma unroll
    for (int f = 0; f < 2; f++) {
        #pragma unroll
        for (int n = 0; n < 8; n++) {
            #pragma unroll
            for (int e = 0; e < 4; e++) {
                float v = acc[f][n][e];
                if (v > THRESH) {
                    int row = rowBase + wr*32 + f*16 + g + ((e >> 1) << 3);
                    int col = colBase + wc*64 + n*8 + tg*2 + (e & 1);
                    unsigned int ov = ordmap(v);
                    int p = atomicAdd(&g_ccnt[row], 1);
                    if (p < CAP) {
                        g_cval[(size_t)row*CAP + p] = ov;
                        g_ccol[(size_t)row*CAP + p] = (unsigned int)col;
                    }
                    if (mirror) {
                        int q = atomicAdd(&g_ccnt[col], 1);
                        if (q < CAP) {
                            g_cval[(size_t)col*CAP + q] = ov;
                            g_ccol[(size_t)col*CAP + q] = (unsigned int)row;
                        }
                    }
                }
            }
        }
    }
}

// ---------------- 3b. refine: exact fp32 values for all candidates ----------------
// 1 warp/row. Row vector in registers (float4/lane); each candidate: coalesced
// 512B col load, 4 FMA, deterministic shfl tree reduce. Overwrites g_cval.
__global__ void __launch_bounds__(256) refine_kernel() {
    int r = blockIdx.x * 8 + (threadIdx.x >> 5);
    int lane = threadIdx.x & 31;
    if (r >= NN) return;
    int c = g_ccnt[r];
    if (c < KK || c > CAP) return;     // fallback path owns these rows
    float4 rv = ((const float4*)(g_xn + (size_t)r * DD))[lane];
    unsigned int* dst = g_cval + (size_t)r * CAP;
    const unsigned int* cols = g_ccol + (size_t)r * CAP;
    #pragma unroll 2
    for (int i = 0; i < c; i++) {
        int col = (int)cols[i];
        float4 cv = ((const float4*)(g_xn + (size_t)col * DD))[lane];
        float s = rv.x*cv.x + rv.y*cv.y + rv.z*cv.z + rv.w*cv.w;
        #pragma unroll
        for (int o = 16; o; o >>= 1) s += __shfl_xor_sync(0xffffffffu, s, o);
        if (lane == 0) dst[i] = ordmap(s);
    }
}

// ---------------- 4. select top-20 (1 warp / row, exact u32 values) ----------------
__global__ void __launch_bounds__(256) select_kernel() {
    int r = blockIdx.x * 8 + (threadIdx.x >> 5);
    int lane = threadIdx.x & 31;
    if (r >= NN) return;
    int c = g_ccnt[r];
    if (c < KK || c > CAP) {
        if (lane == 0) {
            int p = atomicAdd(&g_fbcnt, 1);
            g_fblist[p] = r;
        }
        return;
    }
    const unsigned int* src = g_cval + (size_t)r * CAP;
    unsigned int v[24];
    #pragma unroll
    for (int i = 0; i < 24; i++) {
        int idx = lane + i*32;
        v[i] = (idx < c) ? src[idx] : 0u;
    }
    unsigned int m = 0;
    #pragma unroll
    for (int i = 0; i < 24; i++) m = max(m, v[i]);

    for (int sel = 0; sel < KK; sel++) {
        unsigned int wm = m;
        #pragma unroll
        for (int o = 16; o; o >>= 1)
            wm = max(wm, __shfl_xor_sync(0xffffffffu, wm, o));
        unsigned int ball = __ballot_sync(0xffffffffu, m == wm);
        int owner = __ffs(ball) - 1;
        if (lane == owner) {
            #pragma unroll
            for (int i = 0; i < 24; i++) {
                if (v[i] == wm) {
                    v[i] = 0u;
                    int idx = lane + i*32;
                    g_topv[r*KK + sel] = ordunmap(wm);
                    g_topi[r*KK + sel] = (int)g_ccol[(size_t)r*CAP + idx];
                    break;
                }
            }
            m = 0;
            #pragma unroll
            for (int i = 0; i < 24; i++) m = max(m, v[i]);
        }
    }
}

// ---------------- 5. fallback: exact fp32 recompute ----------------
__global__ void __launch_bounds__(256) fallback_kernel() {
    __shared__ unsigned long long red[256];
    float* rowbuf = g_fbrow + (size_t)blockIdx.x * NN;
    int n = g_fbcnt;
    int t = threadIdx.x;
    for (int ii = blockIdx.x; ii < n; ii += gridDim.x) {
        int r = g_fblist[ii];
        const float* xr = g_xn + (size_t)r * DD;
        for (int col = t; col < NN; col += 256) {
            const float* xc = g_xn + (size_t)col * DD;
            float s = 0.f;
            #pragma unroll 16
            for (int k = 0; k < DD; k++) s += xr[k] * xc[k];
            rowbuf[col] = s;
        }
        __syncthreads();
        for (int sel = 0; sel < KK; sel++) {
            unsigned long long best = 0ULL;
            for (int col = t; col < NN; col += 256) {
                unsigned long long pk =
                    ((unsigned long long)ordmap(rowbuf[col]) << 32) | (unsigned int)col;
                if (pk > best) best = pk;
            }
            red[t] = best;
            __syncthreads();
            for (int d = 128; d > 0; d >>= 1) {
                if (t < d && red[t + d] > red[t]) red[t] = red[t + d];
                __syncthreads();
            }
            if (t == 0) {
                unsigned long long b = red[0];
                int bi = (int)(b & 0xFFFFFFFFu);
                g_topv[r*KK + sel] = ordunmap((unsigned int)(b >> 32));
                g_topi[r*KK + sel] = bi;
                rowbuf[bi] = -2.f;
            }
            __syncthreads();
        }
        __syncthreads();
    }
}

// ---------------- 6. degree + in-count ----------------
__global__ void deg_kernel() {
    int r = blockIdx.x * blockDim.x + threadIdx.x;
    if (r >= NN) return;
    bool self = false;
    #pragma unroll
    for (int k = 0; k < KK; k++) {
        int c = g_topi[r*KK + k];
        float w = g_topv[r*KK + k];
        if (c == r) self = true;
        atomicAdd(&g_deg[c], w);
        atomicAdd(&g_cnt[c], 1);
    }
    atomicAdd(&g_deg[r], self ? 0.f : 1.f);
    atomicAdd(&g_cnt[r], 1);
}

// ---------------- 7. exclusive scan of cnt -> off ----------------
__global__ void __launch_bounds__(1024) scan_kernel() {
    __shared__ int partial[1024];
    int t = threadIdx.x;
    int base = t * 12;
    int local[12];
    int s = 0;
    #pragma unroll
    for (int i = 0; i < 12; i++) { local[i] = s; s += g_cnt[base + i]; }
    partial[t] = s;
    __syncthreads();
    for (int d = 1; d < 1024; d <<= 1) {
        int v = (t >= d) ? partial[t - d] : 0;
        __syncthreads();
        partial[t] += v;
        __syncthreads();
    }
    int chunk_off = (t == 0) ? 0 : partial[t - 1];
    #pragma unroll
    for (int i = 0; i < 12; i++) {
        int o = chunk_off + local[i];
        g_off[base + i] = o;
        g_fill[base + i] = o;
    }
    if (t == 1023) g_off[NN] = partial[1023];
}

// ---------------- 8. dis ----------------
__global__ void dis_kernel() {
    int i = blockIdx.x * blockDim.x + threadIdx.x;
    if (i >= NN) return;
    float d = g_deg[i];
    g_dis[i] = (d > 0.f) ? (1.0f / sqrtf(fmaxf(d, 1e-30f))) : 0.f;
}

// ---------------- 9. build transposed CSR ----------------
__global__ void fill_kernel() {
    int r = blockIdx.x * blockDim.x + threadIdx.x;
    if (r >= NN) return;
    float dr = g_dis[r];
    bool self = false;
    #pragma unroll
    for (int k = 0; k < KK; k++) {
        int c = g_topi[r*KK + k];
        float w = g_topv[r*KK + k];
        if (c == r) self = true;
        int p = atomicAdd(&g_fill[c], 1);
        g_esrc[p] = r;
        g_ew[p] = dr * w * g_dis[c];
    }
    float lw = self ? 0.f : 1.f;
    int p = atomicAdd(&g_fill[r], 1);
    g_esrc[p] = r;
    g_ew[p] = dr * dr * lw;
}

// ---------------- 10. dense Y = X @ W ----------------
template <int DOUT, bool FIRST>
__global__ void xw_kernel(const float* __restrict__ xin, const float* __restrict__ W) {
    const float* X = FIRST ? xin : (const float*)g_h;
    float* Y = FIRST ? g_hw1 : g_hw2;
    __shared__ float xs[16][DD];
    int j = threadIdx.x;
    int r0 = blockIdx.x * 16;
    for (int idx = j; idx < 16 * DD; idx += DOUT)
        xs[idx >> 7][idx & 127] = X[(size_t)(r0 + (idx >> 7)) * DD + (idx & 127)];
    __syncthreads();
    float acc[16];
    #pragma unroll
    for (int i = 0; i < 16; i++) acc[i] = 0.f;
    for (int k = 0; k < DD; k++) {
        float w = W[k * DOUT + j];
        #pragma unroll
        for (int i = 0; i < 16; i++) acc[i] += xs[i][k] * w;
    }
    #pragma unroll
    for (int i = 0; i < 16; i++) Y[(size_t)(r0 + i) * DOUT + j] = acc[i];
}

// ---------------- 11. aggregate over in-edges ----------------
template <int DH, bool RELU>
__global__ void agg_kernel(const float* __restrict__ b, float* __restrict__ outp) {
    const float* hw = RELU ? g_hw1 : g_hw2;
    float* dst = RELU ? g_h : outp;
    int c = blockIdx.x;
    int t = threadIdx.x;
    int e0 = g_off[c], e1 = g_off[c + 1];
    float acc = b[t];
    for (int e = e0; e < e1; e++) {
        int s = g_esrc[e];
        float w = g_ew[e];
        acc += w * hw[(size_t)s * DH + t];
    }
    if (RELU) acc = fmaxf(acc, 0.f);
    dst[(size_t)c * DH + t] = acc;
}

// ---------------- launch ----------------
extern "C" void kernel_launch(void* const* d_in, const int* in_sizes, int n_in,
                              void* d_out, int out_size) {
    const float* x  = (const float*)d_in[0];
    const float* W1 = (const float*)d_in[1];
    const float* b1 = (const float*)d_in[2];
    const float* W2 = (const float*)d_in[3];
    const float* b2 = (const float*)d_in[4];
    float* out = (float*)d_out;

    init_kernel<<<(NN + 255)/256, 256>>>();
    normalize_kernel<<<NN/8, 256>>>(x);
    gemm_cand_kernel<<<TRI_BLOCKS, 256>>>();
    refine_kernel<<<NN/8, 256>>>();
    select_kernel<<<NN/8, 256>>>();
    fallback_kernel<<<FB_BLOCKS, 256>>>();
    deg_kernel<<<(NN + 255)/256, 256>>>();
    scan_kernel<<<1, 1024>>>();
    dis_kernel<<<(NN + 255)/256, 256>>>();
    fill_kernel<<<(NN + 255)/256, 256>>>();

    xw_kernel<HID, true><<<NN/16, HID>>>(x, W1);
    agg_kernel<HID, true><<<NN, HID>>>(b1, nullptr);
    xw_kernel<OUTD, false><<<NN/16, OUTD>>>(nullptr, W2);
    agg_kernel<OUTD, false><<<NN, OUTD>>>(b2, out);
    (void)in_sizes; (void)n_in; (void)out_size;
}